// round 1
// baseline (speedup 1.0000x reference)
#include <cuda_runtime.h>
#include <cuda_bf16.h>

// Problem constants: x (B=2, C=256, D=16,H=16,W=16) -> N = 4096 spatial.
#define BB   2
#define CC   256
#define NSP  4096
#define GROUPS 32
#define CPG  (CC/GROUPS)          // 8 channels per group
#define GELEMS (CPG*NSP)          // 32768 elements per (batch, group)

// ---------------- scratch (static __device__, no allocations) ----------------
__device__ float g_h [BB*CC*NSP];   // groupnorm output      8 MB
__device__ float g_q [BB*CC*NSP];
__device__ float g_k [BB*CC*NSP];
__device__ float g_v [BB*CC*NSP];
__device__ float g_o [BB*CC*NSP];   // attn @ V
__device__ float g_attn[33554432];  // B*N*N = 2*4096*4096   128 MB

// ============================ GroupNorm =====================================
__global__ __launch_bounds__(256) void gn_kernel(
    const float* __restrict__ x, const float* __restrict__ w,
    const float* __restrict__ b)
{
    int batch = blockIdx.x >> 5;
    int g     = blockIdx.x & 31;
    size_t base = ((size_t)batch*CC + (size_t)g*CPG) * NSP;
    const float* xp = x + base;

    float s = 0.f, ss = 0.f;
    for (int i = threadIdx.x; i < GELEMS; i += 256) {
        float v = xp[i];
        s += v; ss += v*v;
    }
    // block reduce (sum, sumsq)
    #pragma unroll
    for (int o = 16; o > 0; o >>= 1) {
        s  += __shfl_xor_sync(0xffffffffu, s,  o);
        ss += __shfl_xor_sync(0xffffffffu, ss, o);
    }
    __shared__ float sh_s[8], sh_ss[8];
    int lane = threadIdx.x & 31, wid = threadIdx.x >> 5;
    if (lane == 0) { sh_s[wid] = s; sh_ss[wid] = ss; }
    __syncthreads();
    s = 0.f; ss = 0.f;
    #pragma unroll
    for (int i = 0; i < 8; i++) { s += sh_s[i]; ss += sh_ss[i]; }

    const float invn = 1.f / (float)GELEMS;
    float mean = s * invn;
    float var  = ss * invn - mean*mean;
    float inv  = rsqrtf(var + 1e-5f);

    for (int i = threadIdx.x; i < GELEMS; i += 256) {
        int c = g*CPG + (i >> 12);   // i/4096
        g_h[base + i] = (xp[i] - mean) * inv * w[c] + b[c];
    }
}

// ====================== GEMM 1: Out[o][n] = W[o][:] . Bm[:][n] ==============
// W row-major (256x256, K contiguous). Bm is (C,N) per batch (n contiguous).
// Used for Q/K/V projections and the final proj (with bias + optional residual).
__global__ __launch_bounds__(256) void gemm_ws_kernel(
    const float* __restrict__ W, const float* __restrict__ bias,
    const float* __restrict__ Bm, float* __restrict__ Out,
    const float* __restrict__ resid)
{
    const int K = CC;
    int n0 = blockIdx.x * 64;
    int o0 = blockIdx.y * 64;
    int bz = blockIdx.z;
    const float* Bp = Bm + (size_t)bz*CC*NSP;
    float*       Op = Out + (size_t)bz*CC*NSP;

    __shared__ float As[16][68];   // [k][o], padded stride
    __shared__ float Bs[16][64];   // [k][n]
    float acc[4][4] = {};
    int tid = threadIdx.x, tx = tid & 15, ty = tid >> 4;

    for (int k0 = 0; k0 < K; k0 += 16) {
        #pragma unroll
        for (int i = 0; i < 4; i++) {
            int idx = tid + i*256;
            int oo = idx >> 4, kk = idx & 15;
            As[kk][oo] = W[(o0+oo)*K + k0 + kk];
        }
        #pragma unroll
        for (int i = 0; i < 4; i++) {
            int idx = tid + i*256;
            int kk = idx >> 6, nn = idx & 63;
            Bs[kk][nn] = Bp[(size_t)(k0+kk)*NSP + n0 + nn];
        }
        __syncthreads();
        #pragma unroll
        for (int kk = 0; kk < 16; kk++) {
            float4 a4 = *(const float4*)(&As[kk][ty*4]);
            float4 b4 = *(const float4*)(&Bs[kk][tx*4]);
            float a[4] = {a4.x,a4.y,a4.z,a4.w};
            float b[4] = {b4.x,b4.y,b4.z,b4.w};
            #pragma unroll
            for (int i = 0; i < 4; i++)
                #pragma unroll
                for (int j = 0; j < 4; j++)
                    acc[i][j] += a[i]*b[j];
        }
        __syncthreads();
    }
    #pragma unroll
    for (int i = 0; i < 4; i++) {
        int o = o0 + ty*4 + i;
        float bi = bias[o];
        #pragma unroll
        for (int j = 0; j < 4; j++) {
            int n = n0 + tx*4 + j;
            float r = acc[i][j] + bi;
            size_t off = (size_t)o*NSP + n;
            if (resid) r += resid[(size_t)bz*CC*NSP + off];
            Op[off] = r;
        }
    }
}

// ============ GEMM 2: S[n][m] = scale * sum_c q[c][n]*k[c][m] ===============
__global__ __launch_bounds__(256) void gemm_qk_kernel(
    const float* __restrict__ q, const float* __restrict__ k, float scale)
{
    int m0 = blockIdx.x * 64;
    int n0 = blockIdx.y * 64;
    int bz = blockIdx.z;
    const float* qp = q + (size_t)bz*CC*NSP;
    const float* kp = k + (size_t)bz*CC*NSP;

    __shared__ float As[16][64];   // [c][n]
    __shared__ float Bs[16][64];   // [c][m]
    float acc[4][4] = {};
    int tid = threadIdx.x, tx = tid & 15, ty = tid >> 4;

    for (int c0 = 0; c0 < CC; c0 += 16) {
        #pragma unroll
        for (int i = 0; i < 4; i++) {
            int idx = tid + i*256;
            int kk = idx >> 6, nn = idx & 63;
            As[kk][nn] = qp[(size_t)(c0+kk)*NSP + n0 + nn];
            Bs[kk][nn] = kp[(size_t)(c0+kk)*NSP + m0 + nn];
        }
        __syncthreads();
        #pragma unroll
        for (int kk = 0; kk < 16; kk++) {
            float4 a4 = *(const float4*)(&As[kk][ty*4]);
            float4 b4 = *(const float4*)(&Bs[kk][tx*4]);
            float a[4] = {a4.x,a4.y,a4.z,a4.w};
            float b[4] = {b4.x,b4.y,b4.z,b4.w};
            #pragma unroll
            for (int i = 0; i < 4; i++)
                #pragma unroll
                for (int j = 0; j < 4; j++)
                    acc[i][j] += a[i]*b[j];
        }
        __syncthreads();
    }
    #pragma unroll
    for (int i = 0; i < 4; i++) {
        size_t row = (size_t)bz*NSP + n0 + ty*4 + i;
        #pragma unroll
        for (int j = 0; j < 4; j++)
            g_attn[row*NSP + m0 + tx*4 + j] = acc[i][j] * scale;
    }
}

// ====================== row softmax over m (4096) ===========================
__global__ __launch_bounds__(256) void softmax_kernel()
{
    size_t row = blockIdx.x;
    float* p = g_attn + row * NSP;
    int t = threadIdx.x;
    float v[16];
    float mx = -1e30f;
    #pragma unroll
    for (int i = 0; i < 16; i++) { v[i] = p[t + i*256]; mx = fmaxf(mx, v[i]); }
    #pragma unroll
    for (int o = 16; o > 0; o >>= 1) mx = fmaxf(mx, __shfl_xor_sync(0xffffffffu, mx, o));
    __shared__ float sred[8];
    int lane = t & 31, wid = t >> 5;
    if (lane == 0) sred[wid] = mx;
    __syncthreads();
    mx = sred[0];
    #pragma unroll
    for (int i = 1; i < 8; i++) mx = fmaxf(mx, sred[i]);
    __syncthreads();

    float s = 0.f;
    #pragma unroll
    for (int i = 0; i < 16; i++) { v[i] = __expf(v[i] - mx); s += v[i]; }
    #pragma unroll
    for (int o = 16; o > 0; o >>= 1) s += __shfl_xor_sync(0xffffffffu, s, o);
    if (lane == 0) sred[wid] = s;
    __syncthreads();
    s = 0.f;
    #pragma unroll
    for (int i = 0; i < 8; i++) s += sred[i];
    float inv = 1.f / s;
    #pragma unroll
    for (int i = 0; i < 16; i++) p[t + i*256] = v[i] * inv;
}

// ========== GEMM 3: out[c][n] = sum_m v[c][m] * attn[n][m] ==================
__global__ __launch_bounds__(256) void gemm_av_kernel(const float* __restrict__ v)
{
    int n0 = blockIdx.x * 64;
    int c0 = blockIdx.y * 64;
    int bz = blockIdx.z;
    const float* vp = v + (size_t)bz*CC*NSP;
    const float* ap = g_attn + (size_t)bz*NSP*NSP;

    __shared__ float As[16][68];   // [m][c]
    __shared__ float Bs[16][68];   // [m][n]
    float acc[4][4] = {};
    int tid = threadIdx.x, tx = tid & 15, ty = tid >> 4;

    for (int m0 = 0; m0 < NSP; m0 += 16) {
        #pragma unroll
        for (int i = 0; i < 4; i++) {
            int idx = tid + i*256;
            int cc = idx >> 4, mm = idx & 15;
            As[mm][cc] = vp[(size_t)(c0+cc)*NSP + m0 + mm];
            Bs[mm][cc] = ap[(size_t)(n0+cc)*NSP + m0 + mm];
        }
        __syncthreads();
        #pragma unroll
        for (int mm = 0; mm < 16; mm++) {
            float4 a4 = *(const float4*)(&As[mm][ty*4]);
            float4 b4 = *(const float4*)(&Bs[mm][tx*4]);
            float a[4] = {a4.x,a4.y,a4.z,a4.w};
            float b[4] = {b4.x,b4.y,b4.z,b4.w};
            #pragma unroll
            for (int i = 0; i < 4; i++)
                #pragma unroll
                for (int j = 0; j < 4; j++)
                    acc[i][j] += a[i]*b[j];
        }
        __syncthreads();
    }
    #pragma unroll
    for (int i = 0; i < 4; i++)
        #pragma unroll
        for (int j = 0; j < 4; j++)
            g_o[((size_t)bz*CC + c0 + ty*4 + i)*NSP + n0 + tx*4 + j] = acc[i][j];
}

// ============================== launch ======================================
extern "C" void kernel_launch(void* const* d_in, const int* in_sizes, int n_in,
                              void* d_out, int out_size)
{
    const float* x    = (const float*)d_in[0];
    const float* gn_w = (const float*)d_in[1];
    const float* gn_b = (const float*)d_in[2];
    const float* wq   = (const float*)d_in[3];
    const float* bq   = (const float*)d_in[4];
    const float* wk   = (const float*)d_in[5];
    const float* bk   = (const float*)d_in[6];
    const float* wv   = (const float*)d_in[7];
    const float* bv   = (const float*)d_in[8];
    const float* wp   = (const float*)d_in[9];
    const float* bp   = (const float*)d_in[10];
    float* out = (float*)d_out;

    void *ph, *pq, *pk, *pv, *po;
    cudaGetSymbolAddress(&ph, g_h);
    cudaGetSymbolAddress(&pq, g_q);
    cudaGetSymbolAddress(&pk, g_k);
    cudaGetSymbolAddress(&pv, g_v);
    cudaGetSymbolAddress(&po, g_o);

    gn_kernel<<<BB*GROUPS, 256>>>(x, gn_w, gn_b);

    dim3 gWS(NSP/64, CC/64, BB);                  // (64, 4, 2)
    gemm_ws_kernel<<<gWS, 256>>>(wq, bq, (const float*)ph, (float*)pq, nullptr);
    gemm_ws_kernel<<<gWS, 256>>>(wk, bk, (const float*)ph, (float*)pk, nullptr);
    gemm_ws_kernel<<<gWS, 256>>>(wv, bv, (const float*)ph, (float*)pv, nullptr);

    dim3 gQK(NSP/64, NSP/64, BB);                 // (64, 64, 2)
    gemm_qk_kernel<<<gQK, 256>>>((const float*)pq, (const float*)pk, 0.0625f);

    softmax_kernel<<<BB*NSP, 256>>>();

    gemm_av_kernel<<<gWS, 256>>>((const float*)pv);

    gemm_ws_kernel<<<gWS, 256>>>(wp, bp, (const float*)po, out, x);
}

// round 2
// speedup vs baseline: 2.4153x; 2.4153x over previous
#include <cuda_runtime.h>
#include <cuda_bf16.h>
#include <cstdint>

// Problem constants: x (B=2, C=256, D=16,H=16,W=16) -> N = 4096 spatial.
#define BB   2
#define CC   256
#define NSP  4096
#define GROUPS 32
#define CPG  (CC/GROUPS)          // 8 channels per group
#define GELEMS (CPG*NSP)          // 32768 elements per (batch, group)

// ---------------- scratch (static __device__, no allocations) ----------------
__device__ float g_h [BB*CC*NSP];   // groupnorm output      8 MB
__device__ float g_q [BB*CC*NSP];
__device__ float g_k [BB*CC*NSP];
__device__ float g_v [BB*CC*NSP];
__device__ float g_o [BB*CC*NSP];   // attn @ V
__device__ float g_attn[33554432];  // B*N*N = 2*4096*4096   128 MB

// ============================ GroupNorm =====================================
__global__ __launch_bounds__(256) void gn_kernel(
    const float* __restrict__ x, const float* __restrict__ w,
    const float* __restrict__ b)
{
    int batch = blockIdx.x >> 5;
    int g     = blockIdx.x & 31;
    size_t base = ((size_t)batch*CC + (size_t)g*CPG) * NSP;
    const float4* xp4 = (const float4*)(x + base);

    float s = 0.f, ss = 0.f;
    for (int i = threadIdx.x; i < GELEMS/4; i += 256) {
        float4 v = xp4[i];
        s  += v.x + v.y + v.z + v.w;
        ss += v.x*v.x + v.y*v.y + v.z*v.z + v.w*v.w;
    }
    #pragma unroll
    for (int o = 16; o > 0; o >>= 1) {
        s  += __shfl_xor_sync(0xffffffffu, s,  o);
        ss += __shfl_xor_sync(0xffffffffu, ss, o);
    }
    __shared__ float sh_s[8], sh_ss[8];
    int lane = threadIdx.x & 31, wid = threadIdx.x >> 5;
    if (lane == 0) { sh_s[wid] = s; sh_ss[wid] = ss; }
    __syncthreads();
    s = 0.f; ss = 0.f;
    #pragma unroll
    for (int i = 0; i < 8; i++) { s += sh_s[i]; ss += sh_ss[i]; }

    const float invn = 1.f / (float)GELEMS;
    float mean = s * invn;
    float var  = ss * invn - mean*mean;
    float inv  = rsqrtf(var + 1e-5f);

    float4* hp4 = (float4*)(g_h + base);
    for (int i = threadIdx.x; i < GELEMS/4; i += 256) {
        int c = g*CPG + (i >> 10);   // (i*4)/4096
        float sc = inv * w[c], of = b[c];
        float4 v = xp4[i];
        v.x = (v.x - mean) * sc + of;
        v.y = (v.y - mean) * sc + of;
        v.z = (v.z - mean) * sc + of;
        v.w = (v.w - mean) * sc + of;
        hp4[i] = v;
    }
}

// =================== TF32 tensor-core GEMM (templated layouts) ==============
// Logical:  C[m][n] = alpha * sum_k A(m,k) * B(k,n)  (+ bias[m]) (+ resid)
//   AT=false: A(m,k) = A[m*lda + k]     AT=true: A(m,k) = A[k*lda + m]
//   BT=false: B(k,n) = B[k*ldb + n]     BT=true: B(k,n) = B[n*ldb + k]
// Tiles: CTA 128x128x32, 8 warps as 2(m) x 4(n); warp tile 64x32;
//        per warp 4x4 mma tiles of m16n8k8 tf32.
__device__ __forceinline__ void mma_tf32(float c[4],
    uint32_t a0, uint32_t a1, uint32_t a2, uint32_t a3,
    uint32_t b0, uint32_t b1)
{
    asm volatile(
        "mma.sync.aligned.m16n8k8.row.col.f32.tf32.tf32.f32 "
        "{%0,%1,%2,%3}, {%4,%5,%6,%7}, {%8,%9}, {%0,%1,%2,%3};\n"
        : "+f"(c[0]), "+f"(c[1]), "+f"(c[2]), "+f"(c[3])
        : "r"(a0), "r"(a1), "r"(a2), "r"(a3), "r"(b0), "r"(b1));
}

template<bool AT, bool BT>
__global__ __launch_bounds__(256) void gemm_tc(
    const float* __restrict__ A, long long lda, long long strideA,
    const float* __restrict__ B, long long ldb, long long strideB,
    float* __restrict__ C, long long ldc, long long strideC,
    const float* __restrict__ bias,
    const float* __restrict__ resid, long long strideR,
    float alpha, int K)
{
    const int bn = blockIdx.x * 128;
    const int bm = blockIdx.y * 128;
    const int bz = blockIdx.z;
    A += (long long)bz * strideA;
    B += (long long)bz * strideB;
    C += (long long)bz * strideC;
    if (resid) resid += (long long)bz * strideR;

    __shared__ float As[32][132];   // [k][m]
    __shared__ float Bs[32][132];   // [k][n]

    const int tid  = threadIdx.x;
    const int wid  = tid >> 5;
    const int lane = tid & 31;
    const int wm   = wid & 1;       // 0..1  -> m offset wm*64
    const int wn   = wid >> 1;      // 0..3  -> n offset wn*32
    const int gid  = lane >> 2;     // 0..7
    const int tg   = lane & 3;      // 0..3

    float acc[16][4];
    #pragma unroll
    for (int i = 0; i < 16; i++)
        #pragma unroll
        for (int j = 0; j < 4; j++) acc[i][j] = 0.f;

    for (int k0 = 0; k0 < K; k0 += 32) {
        // ---- stage A tile -> As[k][m] ----
        if (AT) {
            int kk = tid >> 5;            // 0..7
            int mm = (tid & 31) * 4;      // 0..124
            #pragma unroll
            for (int r = 0; r < 4; r++) {
                float4 t4 = *(const float4*)&A[(long long)(k0 + kk + r*8) * lda + bm + mm];
                *(float4*)&As[kk + r*8][mm] = t4;
            }
        } else {
            int mm = tid >> 3;            // 0..31
            int kk = (tid & 7) * 4;       // 0..28
            #pragma unroll
            for (int r = 0; r < 4; r++) {
                float4 t4 = *(const float4*)&A[(long long)(bm + mm + r*32) * lda + k0 + kk];
                As[kk+0][mm + r*32] = t4.x;
                As[kk+1][mm + r*32] = t4.y;
                As[kk+2][mm + r*32] = t4.z;
                As[kk+3][mm + r*32] = t4.w;
            }
        }
        // ---- stage B tile -> Bs[k][n] ----
        if (BT) {
            int nn = tid >> 3;
            int kk = (tid & 7) * 4;
            #pragma unroll
            for (int r = 0; r < 4; r++) {
                float4 t4 = *(const float4*)&B[(long long)(bn + nn + r*32) * ldb + k0 + kk];
                Bs[kk+0][nn + r*32] = t4.x;
                Bs[kk+1][nn + r*32] = t4.y;
                Bs[kk+2][nn + r*32] = t4.z;
                Bs[kk+3][nn + r*32] = t4.w;
            }
        } else {
            int kk = tid >> 5;
            int nn = (tid & 31) * 4;
            #pragma unroll
            for (int r = 0; r < 4; r++) {
                float4 t4 = *(const float4*)&B[(long long)(k0 + kk + r*8) * ldb + bn + nn];
                *(float4*)&Bs[kk + r*8][nn] = t4;
            }
        }
        __syncthreads();

        #pragma unroll
        for (int ks = 0; ks < 32; ks += 8) {
            uint32_t af[4][4];
            #pragma unroll
            for (int mi = 0; mi < 4; mi++) {
                int mrow = wm*64 + mi*16 + gid;
                af[mi][0] = __float_as_uint(As[ks + tg    ][mrow    ]);
                af[mi][1] = __float_as_uint(As[ks + tg    ][mrow + 8]);
                af[mi][2] = __float_as_uint(As[ks + tg + 4][mrow    ]);
                af[mi][3] = __float_as_uint(As[ks + tg + 4][mrow + 8]);
            }
            uint32_t bf[4][2];
            #pragma unroll
            for (int ni = 0; ni < 4; ni++) {
                int ncol = wn*32 + ni*8 + gid;
                bf[ni][0] = __float_as_uint(Bs[ks + tg    ][ncol]);
                bf[ni][1] = __float_as_uint(Bs[ks + tg + 4][ncol]);
            }
            #pragma unroll
            for (int mi = 0; mi < 4; mi++)
                #pragma unroll
                for (int ni = 0; ni < 4; ni++)
                    mma_tf32(acc[mi*4 + ni],
                             af[mi][0], af[mi][1], af[mi][2], af[mi][3],
                             bf[ni][0], bf[ni][1]);
        }
        __syncthreads();
    }

    // ---- epilogue ----
    #pragma unroll
    for (int mi = 0; mi < 4; mi++) {
        int m0 = bm + wm*64 + mi*16 + gid;
        int m1 = m0 + 8;
        float bi0 = bias ? bias[m0] : 0.f;
        float bi1 = bias ? bias[m1] : 0.f;
        #pragma unroll
        for (int ni = 0; ni < 4; ni++) {
            int n = bn + wn*32 + ni*8 + tg*2;
            const float* c = acc[mi*4 + ni];
            float2 r0, r1;
            r0.x = c[0]*alpha + bi0;  r0.y = c[1]*alpha + bi0;
            r1.x = c[2]*alpha + bi1;  r1.y = c[3]*alpha + bi1;
            long long off0 = (long long)m0*ldc + n;
            long long off1 = (long long)m1*ldc + n;
            if (resid) {
                float2 x0 = *(const float2*)&resid[off0];
                float2 x1 = *(const float2*)&resid[off1];
                r0.x += x0.x; r0.y += x0.y;
                r1.x += x1.x; r1.y += x1.y;
            }
            *(float2*)&C[off0] = r0;
            *(float2*)&C[off1] = r1;
        }
    }
}

// ====================== row softmax over m (4096), float4 ===================
__global__ __launch_bounds__(256) void softmax_kernel()
{
    size_t row = blockIdx.x;
    float4* p = (float4*)(g_attn + row * NSP);
    int t = threadIdx.x;
    float4 v[4];
    float mx = -1e30f;
    #pragma unroll
    for (int i = 0; i < 4; i++) {
        v[i] = p[t + i*256];
        mx = fmaxf(mx, fmaxf(fmaxf(v[i].x, v[i].y), fmaxf(v[i].z, v[i].w)));
    }
    #pragma unroll
    for (int o = 16; o > 0; o >>= 1) mx = fmaxf(mx, __shfl_xor_sync(0xffffffffu, mx, o));
    __shared__ float sred[8];
    int lane = t & 31, wid = t >> 5;
    if (lane == 0) sred[wid] = mx;
    __syncthreads();
    mx = sred[0];
    #pragma unroll
    for (int i = 1; i < 8; i++) mx = fmaxf(mx, sred[i]);
    __syncthreads();

    float s = 0.f;
    #pragma unroll
    for (int i = 0; i < 4; i++) {
        v[i].x = __expf(v[i].x - mx); v[i].y = __expf(v[i].y - mx);
        v[i].z = __expf(v[i].z - mx); v[i].w = __expf(v[i].w - mx);
        s += v[i].x + v[i].y + v[i].z + v[i].w;
    }
    #pragma unroll
    for (int o = 16; o > 0; o >>= 1) s += __shfl_xor_sync(0xffffffffu, s, o);
    if (lane == 0) sred[wid] = s;
    __syncthreads();
    s = 0.f;
    #pragma unroll
    for (int i = 0; i < 8; i++) s += sred[i];
    float inv = 1.f / s;
    #pragma unroll
    for (int i = 0; i < 4; i++) {
        v[i].x *= inv; v[i].y *= inv; v[i].z *= inv; v[i].w *= inv;
        p[t + i*256] = v[i];
    }
}

// ============================== launch ======================================
extern "C" void kernel_launch(void* const* d_in, const int* in_sizes, int n_in,
                              void* d_out, int out_size)
{
    const float* x    = (const float*)d_in[0];
    const float* gn_w = (const float*)d_in[1];
    const float* gn_b = (const float*)d_in[2];
    const float* wq   = (const float*)d_in[3];
    const float* bq   = (const float*)d_in[4];
    const float* wk   = (const float*)d_in[5];
    const float* bk   = (const float*)d_in[6];
    const float* wv   = (const float*)d_in[7];
    const float* bv   = (const float*)d_in[8];
    const float* wp   = (const float*)d_in[9];
    const float* bp   = (const float*)d_in[10];
    float* out = (float*)d_out;

    void *ph, *pq, *pk, *pv, *po, *pa;
    cudaGetSymbolAddress(&ph, g_h);
    cudaGetSymbolAddress(&pq, g_q);
    cudaGetSymbolAddress(&pk, g_k);
    cudaGetSymbolAddress(&pv, g_v);
    cudaGetSymbolAddress(&po, g_o);
    cudaGetSymbolAddress(&pa, g_attn);
    const float* h = (const float*)ph;
    float* q = (float*)pq; float* k = (float*)pk; float* v = (float*)pv;
    float* o = (float*)po; float* attn = (float*)pa;

    const long long sBN = (long long)CC*NSP;   // per-batch stride for (C,N) mats
    const long long sAT = (long long)NSP*NSP;  // per-batch stride for attn

    gn_kernel<<<BB*GROUPS, 256>>>(x, gn_w, gn_b);

    // QKV projections: M=C(256), N=NSP, K=C.  A=W row-major, B=h (C,N).
    dim3 gWS(NSP/128, CC/128, BB);             // (32, 2, 2)
    gemm_tc<false,false><<<gWS, 256>>>(wq, CC, 0, h, NSP, sBN, q, NSP, sBN,
                                       bq, nullptr, 0, 1.f, CC);
    gemm_tc<false,false><<<gWS, 256>>>(wk, CC, 0, h, NSP, sBN, k, NSP, sBN,
                                       bk, nullptr, 0, 1.f, CC);
    gemm_tc<false,false><<<gWS, 256>>>(wv, CC, 0, h, NSP, sBN, v, NSP, sBN,
                                       bv, nullptr, 0, 1.f, CC);

    // S[n][m] = scale * sum_c q[c][n] k[c][m]:  M=N=NSP, K=C.  A=q^T, B=k.
    dim3 gQK(NSP/128, NSP/128, BB);            // (32, 32, 2)
    gemm_tc<true,false><<<gQK, 256>>>(q, NSP, sBN, k, NSP, sBN, attn, NSP, sAT,
                                      nullptr, nullptr, 0, 0.0625f, CC);

    softmax_kernel<<<BB*NSP, 256>>>();

    // O[c][n] = sum_m v[c][m] attn[n][m]:  M=C, N=NSP, K=NSP.  A=v, B=attn^T.
    gemm_tc<false,true><<<gWS, 256>>>(v, NSP, sBN, attn, NSP, sAT, o, NSP, sBN,
                                      nullptr, nullptr, 0, 1.f, NSP);

    // out = x + wp @ o + bp
    gemm_tc<false,false><<<gWS, 256>>>(wp, CC, 0, o, NSP, sBN, out, NSP, sBN,
                                       bp, x, sBN, 1.f, CC);
}

// round 3
// speedup vs baseline: 2.6390x; 1.0927x over previous
#include <cuda_runtime.h>
#include <cstdint>
#include <cstddef>

// Problem constants: x (B=2, C=256, D=16,H=16,W=16) -> N = 4096 spatial.
#define BB   2
#define CC   256
#define NSP  4096
#define GROUPS 32
#define CPG  (CC/GROUPS)          // 8 channels per group
#define GELEMS (CPG*NSP)          // 32768 elements per (batch, group)

// ---------------- scratch (static __device__, no allocations) ----------------
__device__ float g_h [BB*CC*NSP];   // groupnorm output      8 MB
__device__ float g_q [BB*CC*NSP];
__device__ float g_k [BB*CC*NSP];
__device__ float g_v [BB*CC*NSP];
__device__ float g_o [BB*CC*NSP];   // attn @ V

// ============================ GroupNorm =====================================
__global__ __launch_bounds__(256) void gn_kernel(
    const float* __restrict__ x, const float* __restrict__ w,
    const float* __restrict__ b)
{
    int batch = blockIdx.x >> 5;
    int g     = blockIdx.x & 31;
    size_t base = ((size_t)batch*CC + (size_t)g*CPG) * NSP;
    const float4* xp4 = (const float4*)(x + base);

    float s = 0.f, ss = 0.f;
    for (int i = threadIdx.x; i < GELEMS/4; i += 256) {
        float4 v = xp4[i];
        s  += v.x + v.y + v.z + v.w;
        ss += v.x*v.x + v.y*v.y + v.z*v.z + v.w*v.w;
    }
    #pragma unroll
    for (int o = 16; o > 0; o >>= 1) {
        s  += __shfl_xor_sync(0xffffffffu, s,  o);
        ss += __shfl_xor_sync(0xffffffffu, ss, o);
    }
    __shared__ float sh_s[8], sh_ss[8];
    int lane = threadIdx.x & 31, wid = threadIdx.x >> 5;
    if (lane == 0) { sh_s[wid] = s; sh_ss[wid] = ss; }
    __syncthreads();
    s = 0.f; ss = 0.f;
    #pragma unroll
    for (int i = 0; i < 8; i++) { s += sh_s[i]; ss += sh_ss[i]; }

    const float invn = 1.f / (float)GELEMS;
    float mean = s * invn;
    float var  = ss * invn - mean*mean;
    float inv  = rsqrtf(var + 1e-5f);

    float4* hp4 = (float4*)(g_h + base);
    for (int i = threadIdx.x; i < GELEMS/4; i += 256) {
        int c = g*CPG + (i >> 10);
        float sc = inv * w[c], of = b[c];
        float4 v = xp4[i];
        v.x = (v.x - mean) * sc + of;
        v.y = (v.y - mean) * sc + of;
        v.z = (v.z - mean) * sc + of;
        v.w = (v.w - mean) * sc + of;
        hp4[i] = v;
    }
}

// ============================ TF32 mma ======================================
__device__ __forceinline__ void mma_tf32(float c[4],
    uint32_t a0, uint32_t a1, uint32_t a2, uint32_t a3,
    uint32_t b0, uint32_t b1)
{
    asm volatile(
        "mma.sync.aligned.m16n8k8.row.col.f32.tf32.tf32.f32 "
        "{%0,%1,%2,%3}, {%4,%5,%6,%7}, {%8,%9}, {%0,%1,%2,%3};\n"
        : "+f"(c[0]), "+f"(c[1]), "+f"(c[2]), "+f"(c[3])
        : "r"(a0), "r"(a1), "r"(a2), "r"(a3), "r"(b0), "r"(b1));
}

__device__ __forceinline__ void cp16(float* dst, const float* src) {
    uint32_t d = (uint32_t)__cvta_generic_to_shared(dst);
    asm volatile("cp.async.cg.shared.global [%0], [%1], 16;" :: "r"(d), "l"(src));
}
#define CP_COMMIT() asm volatile("cp.async.commit_group;")
#define CP_WAIT0()  asm volatile("cp.async.wait_group 0;")
#define CP_WAIT1()  asm volatile("cp.async.wait_group 1;")

// =================== generic TF32 GEMM body (128x128x32 tiles) ==============
// C[m][n] = alpha * sum_k A(m,k) * B(k,n) (+bias[m]) (+resid)
template<bool AT, bool BT>
__device__ __forceinline__ void gemm_body(
    const float* __restrict__ A, int lda,
    const float* __restrict__ B, int ldb,
    float* __restrict__ C, int ldc,
    const float* __restrict__ bias, const float* __restrict__ resid,
    float alpha, int K, int bm, int bn)
{
    __shared__ float As[32][132];
    __shared__ float Bs[32][132];

    const int tid  = threadIdx.x;
    const int wid  = tid >> 5;
    const int lane = tid & 31;
    const int wm   = wid & 1;
    const int wn   = wid >> 1;
    const int gid  = lane >> 2;
    const int tg   = lane & 3;

    float acc[16][4];
    #pragma unroll
    for (int i = 0; i < 16; i++)
        #pragma unroll
        for (int j = 0; j < 4; j++) acc[i][j] = 0.f;

    for (int k0 = 0; k0 < K; k0 += 32) {
        if (AT) {
            int kk = tid >> 5;
            int mm = (tid & 31) * 4;
            #pragma unroll
            for (int r = 0; r < 4; r++) {
                float4 t4 = *(const float4*)&A[(size_t)(k0 + kk + r*8) * lda + bm + mm];
                *(float4*)&As[kk + r*8][mm] = t4;
            }
        } else {
            int mm = tid >> 3;
            int kk = (tid & 7) * 4;
            #pragma unroll
            for (int r = 0; r < 4; r++) {
                float4 t4 = *(const float4*)&A[(size_t)(bm + mm + r*32) * lda + k0 + kk];
                As[kk+0][mm + r*32] = t4.x;
                As[kk+1][mm + r*32] = t4.y;
                As[kk+2][mm + r*32] = t4.z;
                As[kk+3][mm + r*32] = t4.w;
            }
        }
        if (BT) {
            int nn = tid >> 3;
            int kk = (tid & 7) * 4;
            #pragma unroll
            for (int r = 0; r < 4; r++) {
                float4 t4 = *(const float4*)&B[(size_t)(bn + nn + r*32) * ldb + k0 + kk];
                Bs[kk+0][nn + r*32] = t4.x;
                Bs[kk+1][nn + r*32] = t4.y;
                Bs[kk+2][nn + r*32] = t4.z;
                Bs[kk+3][nn + r*32] = t4.w;
            }
        } else {
            int kk = tid >> 5;
            int nn = (tid & 31) * 4;
            #pragma unroll
            for (int r = 0; r < 4; r++) {
                float4 t4 = *(const float4*)&B[(size_t)(k0 + kk + r*8) * ldb + bn + nn];
                *(float4*)&Bs[kk + r*8][nn] = t4;
            }
        }
        __syncthreads();

        #pragma unroll
        for (int ks = 0; ks < 32; ks += 8) {
            uint32_t af[4][4];
            #pragma unroll
            for (int mi = 0; mi < 4; mi++) {
                int mrow = wm*64 + mi*16 + gid;
                af[mi][0] = __float_as_uint(As[ks + tg    ][mrow    ]);
                af[mi][1] = __float_as_uint(As[ks + tg    ][mrow + 8]);
                af[mi][2] = __float_as_uint(As[ks + tg + 4][mrow    ]);
                af[mi][3] = __float_as_uint(As[ks + tg + 4][mrow + 8]);
            }
            uint32_t bf[4][2];
            #pragma unroll
            for (int ni = 0; ni < 4; ni++) {
                int ncol = wn*32 + ni*8 + gid;
                bf[ni][0] = __float_as_uint(Bs[ks + tg    ][ncol]);
                bf[ni][1] = __float_as_uint(Bs[ks + tg + 4][ncol]);
            }
            #pragma unroll
            for (int mi = 0; mi < 4; mi++)
                #pragma unroll
                for (int ni = 0; ni < 4; ni++)
                    mma_tf32(acc[mi*4 + ni],
                             af[mi][0], af[mi][1], af[mi][2], af[mi][3],
                             bf[ni][0], bf[ni][1]);
        }
        __syncthreads();
    }

    #pragma unroll
    for (int mi = 0; mi < 4; mi++) {
        int m0 = bm + wm*64 + mi*16 + gid;
        int m1 = m0 + 8;
        float bi0 = bias ? bias[m0] : 0.f;
        float bi1 = bias ? bias[m1] : 0.f;
        #pragma unroll
        for (int ni = 0; ni < 4; ni++) {
            int n = bn + wn*32 + ni*8 + tg*2;
            const float* c = acc[mi*4 + ni];
            float2 r0, r1;
            r0.x = c[0]*alpha + bi0;  r0.y = c[1]*alpha + bi0;
            r1.x = c[2]*alpha + bi1;  r1.y = c[3]*alpha + bi1;
            size_t off0 = (size_t)m0*ldc + n;
            size_t off1 = (size_t)m1*ldc + n;
            if (resid) {
                float2 x0 = *(const float2*)&resid[off0];
                float2 x1 = *(const float2*)&resid[off1];
                r0.x += x0.x; r0.y += x0.y;
                r1.x += x1.x; r1.y += x1.y;
            }
            *(float2*)&C[off0] = r0;
            *(float2*)&C[off1] = r1;
        }
    }
}

// Generic wrapper (used for output projection)
template<bool AT, bool BT>
__global__ __launch_bounds__(256) void gemm_tc(
    const float* __restrict__ A, int lda, long long strideA,
    const float* __restrict__ B, int ldb, long long strideB,
    float* __restrict__ C, int ldc, long long strideC,
    const float* __restrict__ bias,
    const float* __restrict__ resid, long long strideR,
    float alpha, int K)
{
    int bn = blockIdx.x * 128;
    int bm = blockIdx.y * 128;
    int bz = blockIdx.z;
    gemm_body<AT, BT>(A + (size_t)bz*strideA, lda, B + (size_t)bz*strideB, ldb,
                      C + (size_t)bz*strideC, ldc, bias,
                      resid ? resid + (size_t)bz*strideR : nullptr,
                      alpha, K, bm, bn);
}

// Merged QKV: grid.y = 6 -> {q:0-1, k:2-3, v:4-5}
__global__ __launch_bounds__(256) void gemm_qkv(
    const float* __restrict__ h,
    const float* __restrict__ wq, const float* __restrict__ bq,
    const float* __restrict__ wk, const float* __restrict__ bk,
    const float* __restrict__ wv, const float* __restrict__ bv,
    float* __restrict__ q, float* __restrict__ k, float* __restrict__ v)
{
    int sel = blockIdx.y >> 1;
    int bm  = (blockIdx.y & 1) * 128;
    int bn  = blockIdx.x * 128;
    int bz  = blockIdx.z;
    const float* W  = (sel == 0) ? wq : (sel == 1) ? wk : wv;
    const float* bi = (sel == 0) ? bq : (sel == 1) ? bk : bv;
    float*       O  = (sel == 0) ? q  : (sel == 1) ? k  : v;
    gemm_body<false,false>(W, CC, h + (size_t)bz*CC*NSP, NSP,
                           O + (size_t)bz*CC*NSP, NSP, bi, nullptr,
                           1.f, CC, bm, bn);
}

// ======================= fused flash attention ==============================
// Per CTA: 64 query rows (n0..n0+63), stream all 4096 keys in blocks of 64.
// Q,K,V layout in gmem: [batch][C=256][N=4096] (channels-major).
// Smem (floats): Qs[256][68], Ks[256][68], Vs[256][68], Ss[64][68], stats.
#define FL_OFF_Q 0
#define FL_OFF_K 17408
#define FL_OFF_V 34816
#define FL_OFF_S 52224
#define FL_OFF_M 56576
#define FL_OFF_L 56640
#define FL_OFF_R 56704
#define FL_SMEM_BYTES (56768*4)

__global__ __launch_bounds__(256) void flash_kernel()
{
    extern __shared__ float sm[];
    float* Qs = sm + FL_OFF_Q;
    float* Ks = sm + FL_OFF_K;
    float* Vs = sm + FL_OFF_V;
    float* Ss = sm + FL_OFF_S;
    float* m_run = sm + FL_OFF_M;
    float* l_run = sm + FL_OFF_L;
    float* rs    = sm + FL_OFF_R;

    const int n0 = blockIdx.x * 64;
    const int bz = blockIdx.y;
    const float* qp = g_q + (size_t)bz*CC*NSP;
    const float* kp = g_k + (size_t)bz*CC*NSP;
    const float* vp = g_v + (size_t)bz*CC*NSP;
    float*       op = g_o + (size_t)bz*CC*NSP;

    const int tid = threadIdx.x;
    const int wid = tid >> 5, lane = tid & 31;
    const int gid = lane >> 2, tg = lane & 3;
    const int wm = wid & 1;        // rows (n) half: offset wm*32
    const int wn = wid >> 1;       // S: col quarter (wn*16); PV: c quarter (wn*64)

    if (tid < 64) { m_run[tid] = -1e30f; l_run[tid] = 0.f; }

    // prefetch K block 0
    #pragma unroll 4
    for (int i = tid; i < 4096; i += 256) {
        int c = i >> 4, j = i & 15;
        cp16(Ks + c*68 + j*4, kp + (size_t)c*NSP + j*4);
    }
    CP_COMMIT();

    // load Q tile (once)
    #pragma unroll 4
    for (int i = tid; i < 4096; i += 256) {
        int c = i >> 4, j = i & 15;
        *(float4*)(Qs + c*68 + j*4) = *(const float4*)(qp + (size_t)c*NSP + n0 + j*4);
    }

    float acc_o[2][8][4];
    #pragma unroll
    for (int a = 0; a < 2; a++)
        #pragma unroll
        for (int b = 0; b < 8; b++)
            #pragma unroll
            for (int c = 0; c < 4; c++) acc_o[a][b][c] = 0.f;

    const float scale = 0.0625f;   // 1/sqrt(256)

    for (int blk = 0; blk < 64; blk++) {
        const int m0 = blk * 64;
        CP_WAIT0();            // K_blk ready
        __syncthreads();       // (also: Vs free — PV of prev blk done)

        // prefetch V_blk (overlaps S-gemm)
        #pragma unroll 4
        for (int i = tid; i < 4096; i += 256) {
            int c = i >> 4, j = i & 15;
            cp16(Vs + c*68 + j*4, vp + (size_t)c*NSP + m0 + j*4);
        }
        CP_COMMIT();

        // ---- S = Q^T K  (64x64, K-loop over c=256) ----
        float acc_s[2][2][4];
        #pragma unroll
        for (int a = 0; a < 2; a++)
            #pragma unroll
            for (int b = 0; b < 2; b++)
                #pragma unroll
                for (int c = 0; c < 4; c++) acc_s[a][b][c] = 0.f;

        #pragma unroll 4
        for (int ks = 0; ks < 256; ks += 8) {
            uint32_t af[2][4];
            #pragma unroll
            for (int mi = 0; mi < 2; mi++) {
                int mrow = wm*32 + mi*16 + gid;
                af[mi][0] = __float_as_uint(Qs[(ks+tg  )*68 + mrow    ]);
                af[mi][1] = __float_as_uint(Qs[(ks+tg  )*68 + mrow + 8]);
                af[mi][2] = __float_as_uint(Qs[(ks+tg+4)*68 + mrow    ]);
                af[mi][3] = __float_as_uint(Qs[(ks+tg+4)*68 + mrow + 8]);
            }
            uint32_t bf[2][2];
            #pragma unroll
            for (int ni = 0; ni < 2; ni++) {
                int ncol = wn*16 + ni*8 + gid;
                bf[ni][0] = __float_as_uint(Ks[(ks+tg  )*68 + ncol]);
                bf[ni][1] = __float_as_uint(Ks[(ks+tg+4)*68 + ncol]);
            }
            #pragma unroll
            for (int mi = 0; mi < 2; mi++)
                #pragma unroll
                for (int ni = 0; ni < 2; ni++)
                    mma_tf32(acc_s[mi][ni], af[mi][0], af[mi][1], af[mi][2], af[mi][3],
                             bf[ni][0], bf[ni][1]);
        }

        // scatter S*scale to Ss[n][m]
        #pragma unroll
        for (int mi = 0; mi < 2; mi++) {
            int r0 = wm*32 + mi*16 + gid, r1 = r0 + 8;
            #pragma unroll
            for (int ni = 0; ni < 2; ni++) {
                int c0 = wn*16 + ni*8 + 2*tg;
                float* cc = acc_s[mi][ni];
                *(float2*)(Ss + r0*68 + c0) = make_float2(cc[0]*scale, cc[1]*scale);
                *(float2*)(Ss + r1*68 + c0) = make_float2(cc[2]*scale, cc[3]*scale);
            }
        }
        __syncthreads();

        // ---- online softmax: 4 threads per row, 16 cols each ----
        {
            int row = tid >> 2, cg = tid & 3;
            float* srow = Ss + row*68 + cg*16;
            float vbuf[16];
            float mx = -1e30f;
            #pragma unroll
            for (int i = 0; i < 16; i++) { vbuf[i] = srow[i]; mx = fmaxf(mx, vbuf[i]); }
            mx = fmaxf(mx, __shfl_xor_sync(0xffffffffu, mx, 1));
            mx = fmaxf(mx, __shfl_xor_sync(0xffffffffu, mx, 2));
            float mold = m_run[row];
            float mnew = fmaxf(mold, mx);
            float psum = 0.f;
            #pragma unroll
            for (int i = 0; i < 16; i++) {
                float p = __expf(vbuf[i] - mnew);
                srow[i] = p;
                psum += p;
            }
            psum += __shfl_xor_sync(0xffffffffu, psum, 1);
            psum += __shfl_xor_sync(0xffffffffu, psum, 2);
            if (cg == 0) {
                float r = __expf(mold - mnew);
                rs[row] = r;
                l_run[row] = l_run[row]*r + psum;
                m_run[row] = mnew;
            }
        }
        __syncthreads();

        // rescale O accumulator by rs[row]
        #pragma unroll
        for (int mi = 0; mi < 2; mi++) {
            int r0 = wm*32 + mi*16 + gid;
            float f0 = rs[r0], f1 = rs[r0 + 8];
            #pragma unroll
            for (int ci = 0; ci < 8; ci++) {
                acc_o[mi][ci][0] *= f0; acc_o[mi][ci][1] *= f0;
                acc_o[mi][ci][2] *= f1; acc_o[mi][ci][3] *= f1;
            }
        }

        // prefetch K_{blk+1} (overlaps PV-gemm)
        if (blk < 63) {
            const int m1 = m0 + 64;
            #pragma unroll 4
            for (int i = tid; i < 4096; i += 256) {
                int c = i >> 4, j = i & 15;
                cp16(Ks + c*68 + j*4, kp + (size_t)c*NSP + m1 + j*4);
            }
        }
        CP_COMMIT();
        CP_WAIT1();            // V_blk ready (K_{blk+1} may be in flight)
        __syncthreads();

        // ---- O += P V^T : out tile 64(n) x 256(c), k = 64 keys ----
        #pragma unroll
        for (int ks = 0; ks < 64; ks += 8) {
            uint32_t af[2][4];
            #pragma unroll
            for (int mi = 0; mi < 2; mi++) {
                int mrow = wm*32 + mi*16 + gid;
                af[mi][0] = __float_as_uint(Ss[mrow*68     + ks+tg  ]);
                af[mi][1] = __float_as_uint(Ss[(mrow+8)*68 + ks+tg  ]);
                af[mi][2] = __float_as_uint(Ss[mrow*68     + ks+tg+4]);
                af[mi][3] = __float_as_uint(Ss[(mrow+8)*68 + ks+tg+4]);
            }
            #pragma unroll
            for (int ci = 0; ci < 8; ci++) {
                int ncol = wn*64 + ci*8 + gid;
                uint32_t b0 = __float_as_uint(Vs[ncol*68 + ks+tg  ]);
                uint32_t b1 = __float_as_uint(Vs[ncol*68 + ks+tg+4]);
                #pragma unroll
                for (int mi = 0; mi < 2; mi++)
                    mma_tf32(acc_o[mi][ci], af[mi][0], af[mi][1], af[mi][2], af[mi][3],
                             b0, b1);
            }
        }
        __syncthreads();
    }

    // ---- epilogue: normalize by l, write O[c][n] ----
    #pragma unroll
    for (int mi = 0; mi < 2; mi++) {
        int r0 = wm*32 + mi*16 + gid, r1 = r0 + 8;
        float inv0 = 1.f / l_run[r0], inv1 = 1.f / l_run[r1];
        #pragma unroll
        for (int ci = 0; ci < 8; ci++) {
            int c0 = wn*64 + ci*8 + 2*tg;
            float* cc = acc_o[mi][ci];
            op[(size_t)(c0  )*NSP + n0 + r0] = cc[0]*inv0;
            op[(size_t)(c0+1)*NSP + n0 + r0] = cc[1]*inv0;
            op[(size_t)(c0  )*NSP + n0 + r1] = cc[2]*inv1;
            op[(size_t)(c0+1)*NSP + n0 + r1] = cc[3]*inv1;
        }
    }
}

// ============================== launch ======================================
extern "C" void kernel_launch(void* const* d_in, const int* in_sizes, int n_in,
                              void* d_out, int out_size)
{
    const float* x    = (const float*)d_in[0];
    const float* gn_w = (const float*)d_in[1];
    const float* gn_b = (const float*)d_in[2];
    const float* wq   = (const float*)d_in[3];
    const float* bq   = (const float*)d_in[4];
    const float* wk   = (const float*)d_in[5];
    const float* bk   = (const float*)d_in[6];
    const float* wv   = (const float*)d_in[7];
    const float* bv   = (const float*)d_in[8];
    const float* wp   = (const float*)d_in[9];
    const float* bp   = (const float*)d_in[10];
    float* out = (float*)d_out;

    void *ph, *pq, *pk, *pv, *po;
    cudaGetSymbolAddress(&ph, g_h);
    cudaGetSymbolAddress(&pq, g_q);
    cudaGetSymbolAddress(&pk, g_k);
    cudaGetSymbolAddress(&pv, g_v);
    cudaGetSymbolAddress(&po, g_o);
    const float* h = (const float*)ph;
    float* q = (float*)pq; float* k = (float*)pk; float* v = (float*)pv;
    float* o = (float*)po;

    const long long sBN = (long long)CC*NSP;

    cudaFuncSetAttribute(flash_kernel,
        cudaFuncAttributeMaxDynamicSharedMemorySize, FL_SMEM_BYTES);

    gn_kernel<<<BB*GROUPS, 256>>>(x, gn_w, gn_b);

    dim3 gQKV(NSP/128, 6, BB);                  // (32, 6, 2) = 384 CTAs
    gemm_qkv<<<gQKV, 256>>>(h, wq, bq, wk, bk, wv, bv, q, k, v);

    dim3 gFL(NSP/64, BB);                       // (64, 2) = 128 CTAs
    flash_kernel<<<gFL, 256, FL_SMEM_BYTES>>>();

    dim3 gP(NSP/128, CC/128, BB);               // (32, 2, 2)
    gemm_tc<false,false><<<gP, 256>>>(wp, CC, 0, o, NSP, sBN, out, NSP, sBN,
                                      bp, x, sBN, 1.f, CC);
}